// round 7
// baseline (speedup 1.0000x reference)
#include <cuda_runtime.h>
#include <stdint.h>

#define B_ 16
#define P_ 25
#define S_ 1024
#define D_ 128
#define H_ 8
#define DH_ 16
#define DFF_ 512
#define BP_ (B_*P_)
#define SIGMA_ 0.1f
#define OMEGA_ 0.5f

// output layout (flat f32 concat of the reference tuple)
#define OFF_R    0
#define OFF_Z    51200
#define OFF_PRED 102400
#define OFF_W    102800
#define OFF_K    103200
#define OFF_V    52532000
#define OFF_I    104960800

// scratch (allocation-free: __device__ globals)
__device__ __align__(16) float g_q[BP_*D_];
__device__ __align__(16) float g_knew[BP_*D_];
__device__ __align__(16) float g_vnew[BP_*D_];
__device__ __align__(16) float g_ctx[BP_*D_];
__device__ float g_pred[BP_];
__device__ int   g_idx[BP_];

__device__ __forceinline__ uint32_t rotl32(uint32_t x, int d) {
    return (x << d) | (x >> (32 - d));
}

// Threefry-2x32 with key (0, 42)  [jax.random.key(42)]
__device__ __forceinline__ void threefry_0_42(uint32_t x0, uint32_t x1,
                                              uint32_t& o0, uint32_t& o1) {
    const uint32_t k0 = 0u, k1 = 42u;
    const uint32_t k2 = k0 ^ k1 ^ 0x1BD11BDAu;
    uint32_t v0 = x0 + k0, v1 = x1 + k1;
#define TF_R(r) { v0 += v1; v1 = rotl32(v1, r); v1 ^= v0; }
    TF_R(13) TF_R(15) TF_R(26) TF_R(6)
    v0 += k1; v1 += k2 + 1u;
    TF_R(17) TF_R(29) TF_R(16) TF_R(24)
    v0 += k2; v1 += k0 + 2u;
    TF_R(13) TF_R(15) TF_R(26) TF_R(6)
    v0 += k0; v1 += k1 + 3u;
    TF_R(17) TF_R(29) TF_R(16) TF_R(24)
    v0 += k1; v1 += k2 + 4u;
    TF_R(13) TF_R(15) TF_R(26) TF_R(6)
    v0 += k2; v1 += k0 + 5u;
#undef TF_R
    o0 = v0; o1 = v1;
}

// ---------------------------------------------------------------------------
// Kernel A: batched q/k/v projection. 4 particles per block, 100 blocks x 384.
// Thread n owns one output column of one matrix for all 4 particles.
// ---------------------------------------------------------------------------
__global__ void __launch_bounds__(384) qkv_kernel(
    const float* __restrict__ x,
    const float* __restrict__ Wq, const float* __restrict__ Wk,
    const float* __restrict__ Wv,
    const float* __restrict__ eps_k, const float* __restrict__ eps_v)
{
    __shared__ float sx[4][D_];
    const int bp0 = blockIdx.x * 4;
    const int tid = threadIdx.x;

    for (int i = tid; i < 4*D_; i += 384) {
        int m = i >> 7, d = i & 127;
        sx[m][d] = x[(bp0 + m)*D_ + d];
    }
    __syncthreads();

    const int sel = tid / D_;          // 0:q 1:k 2:v
    const int col = tid & 127;
    const float* W = (sel == 0) ? Wq : (sel == 1) ? Wk : Wv;

    float a0 = 0.f, a1 = 0.f, a2 = 0.f, a3 = 0.f;
    #pragma unroll 8
    for (int d = 0; d < D_; ++d) {
        float wv = W[d*D_ + col];
        a0 += sx[0][d] * wv;
        a1 += sx[1][d] * wv;
        a2 += sx[2][d] * wv;
        a3 += sx[3][d] * wv;
    }
    float acc[4] = {a0, a1, a2, a3};
    #pragma unroll
    for (int m = 0; m < 4; ++m) {
        int o = (bp0 + m)*D_ + col;
        if (sel == 0)      g_q[o]    = acc[m];
        else if (sel == 1) g_knew[o] = acc[m] + SIGMA_ * eps_k[o];
        else               g_vnew[o] = acc[m] + SIGMA_ * eps_v[o];
    }
}

// ---------------------------------------------------------------------------
// Kernel B: per-(b,p) attention. 400 blocks x 512 threads. Streams K and V.
// ---------------------------------------------------------------------------
__global__ void __launch_bounds__(512) attn_kernel(
    const float* __restrict__ K, const float* __restrict__ V,
    const int* __restrict__ tp)
{
    __shared__ float sq[D_], sk[D_], sv[D_];
    __shared__ float sS[H_][S_];
    __shared__ float sred[4][D_];

    const int bp   = blockIdx.x;
    const int tid  = threadIdx.x;
    const int dim  = tid & 127;
    const int grp  = tid >> 7;
    const int warp = tid >> 5;
    const int lane = tid & 31;
    const int t    = tp ? tp[0] : 512;

    if (grp < 3) {
        float* dst = (grp == 0) ? sq : (grp == 1) ? sk : sv;
        const float* src = (grp == 0) ? g_q : (grp == 1) ? g_knew : g_vnew;
        dst[dim] = src[bp*D_ + dim];
    }
    __syncthreads();

    // scores: warp-per-row, lane owns 4 contiguous dims
    {
        const float4* Kbase = reinterpret_cast<const float4*>(K + (size_t)bp * S_ * D_);
        const float4  qf    = reinterpret_cast<const float4*>(sq)[lane];
        const int     head  = lane >> 2;
        #pragma unroll 2
        for (int s = warp; s < t; s += 16) {
            float4 kv = Kbase[(size_t)s * 32 + lane];
            float a = qf.x*kv.x + qf.y*kv.y + qf.z*kv.z + qf.w*kv.w;
            a += __shfl_xor_sync(0xffffffffu, a, 1);
            a += __shfl_xor_sync(0xffffffffu, a, 2);
            if ((lane & 3) == 0) sS[head][s] = a * 0.25f;
        }
    }
    if (tid < H_) {
        float a = 0.f;
        #pragma unroll
        for (int d = 0; d < DH_; ++d) a += sq[tid*DH_ + d] * sk[tid*DH_ + d];
        sS[tid][t] = a * 0.25f;
    }
    __syncthreads();

    // softmax per head
    if (tid < 256) {
        int h = tid >> 5, ln = tid & 31;
        float m = -3.4e38f;
        for (int s = ln; s <= t; s += 32) m = fmaxf(m, sS[h][s]);
        #pragma unroll
        for (int o = 16; o; o >>= 1) m = fmaxf(m, __shfl_xor_sync(0xffffffffu, m, o));
        float sum = 0.f;
        for (int s = ln; s <= t; s += 32) {
            float e = expf(sS[h][s] - m);
            sS[h][s] = e; sum += e;
        }
        #pragma unroll
        for (int o = 16; o; o >>= 1) sum += __shfl_xor_sync(0xffffffffu, sum, o);
        float inv = 1.f / sum;
        for (int s = ln; s <= t; s += 32) sS[h][s] *= inv;
    }
    __syncthreads();

    // ctx: 4-way split over s, unrolled for MLP
    {
        int h = dim >> 4;
        const float* Vrow = V + (size_t)bp * S_ * D_ + dim;
        float c0 = 0.f, c1 = 0.f, c2 = 0.f, c3 = 0.f;
        int s = grp;
        for (; s + 12 < t; s += 16) {
            float v0 = Vrow[(size_t)(s     ) * D_];
            float v1 = Vrow[(size_t)(s +  4) * D_];
            float v2 = Vrow[(size_t)(s +  8) * D_];
            float v3 = Vrow[(size_t)(s + 12) * D_];
            c0 += sS[h][s     ] * v0;
            c1 += sS[h][s +  4] * v1;
            c2 += sS[h][s +  8] * v2;
            c3 += sS[h][s + 12] * v3;
        }
        for (; s <= t; s += 4) {
            float vv = (s == t) ? sv[dim] : Vrow[(size_t)s * D_];
            c0 += sS[h][s] * vv;
        }
        sred[grp][dim] = (c0 + c1) + (c2 + c3);
    }
    __syncthreads();
    if (tid < D_)
        g_ctx[bp*D_ + tid] = sred[0][tid] + sred[1][tid] + sred[2][tid] + sred[3][tid];
}

// ---------------------------------------------------------------------------
// Kernel C: batched MLP head. 4 particles per block, 100 blocks x 512.
// ---------------------------------------------------------------------------
__global__ void __launch_bounds__(512) mlp_kernel(
    const float* __restrict__ Wo,
    const float* __restrict__ W1, const float* __restrict__ b1,
    const float* __restrict__ W2, const float* __restrict__ b2,
    const float* __restrict__ Wout, const float* __restrict__ bout,
    const float* __restrict__ eps_z, float* __restrict__ out)
{
    __shared__ float sctx[4][D_];
    __shared__ float szs[4][D_];
    __shared__ float sh1[DFF_][5];       // padded: conflict-free store
    __shared__ float sr[4][D_];

    const int bp0 = blockIdx.x * 4;
    const int tid = threadIdx.x;
    const int dim = tid & 127;
    const int m   = tid >> 7;            // 0..3

    sctx[m][dim] = g_ctx[(bp0 + m)*D_ + dim];
    __syncthreads();

    // z = ctx @ Wo + sigma*eps_z
    {
        float a = 0.f;
        #pragma unroll 8
        for (int d = 0; d < D_; ++d) a += sctx[m][d] * Wo[d*D_ + dim];
        a += SIGMA_ * eps_z[(bp0 + m)*D_ + dim];
        szs[m][dim] = a;
        out[OFF_Z + (bp0 + m)*D_ + dim] = a;
    }
    __syncthreads();

    // h1 = relu(z @ W1 + b1): thread owns one of 512 columns, 4 particles
    {
        const int f = tid;
        float a0 = b1[f], a1 = a0, a2 = a0, a3 = a0;
        #pragma unroll 8
        for (int d = 0; d < D_; ++d) {
            float wv = W1[d*DFF_ + f];
            a0 += szs[0][d] * wv;
            a1 += szs[1][d] * wv;
            a2 += szs[2][d] * wv;
            a3 += szs[3][d] * wv;
        }
        sh1[f][0] = fmaxf(a0, 0.f);
        sh1[f][1] = fmaxf(a1, 0.f);
        sh1[f][2] = fmaxf(a2, 0.f);
        sh1[f][3] = fmaxf(a3, 0.f);
    }
    __syncthreads();

    // r = h1 @ W2 + b2: thread owns (m, dim), full 512 contraction
    {
        float a = b2[dim];
        #pragma unroll 8
        for (int f = 0; f < DFF_; ++f) a += sh1[f][m] * W2[f*D_ + dim];
        sr[m][dim] = a;
        out[OFF_R + (bp0 + m)*D_ + dim] = a;
    }
    __syncthreads();

    // pred = r @ Wout + bout (F == 1): warps 0..3, one particle each
    const int warp = tid >> 5, lane = tid & 31;
    if (warp < 4) {
        float a = 0.f;
        #pragma unroll
        for (int d = lane; d < D_; d += 32) a += sr[warp][d] * Wout[d];
        #pragma unroll
        for (int o = 16; o; o >>= 1) a += __shfl_xor_sync(0xffffffffu, a, o);
        if (lane == 0) {
            a += bout[0];
            g_pred[bp0 + warp] = a;
            out[OFF_PRED + bp0 + warp] = a;
        }
    }
}

// ---------------------------------------------------------------------------
// Kernel 2: weights + categorical resampling. 16 blocks x 800 (25 warps).
// ---------------------------------------------------------------------------
__global__ void __launch_bounds__(800) resample_kernel(
    const float* __restrict__ y, float* __restrict__ out)
{
    const int b = blockIdx.x;
    const int warp = threadIdx.x >> 5;
    const int lane = threadIdx.x & 31;
    __shared__ float slw[P_];

    if (warp == 0) {
        float logw = 3.4e38f;
        if (lane < P_) {
            float mu = y[b*4] - g_pred[b*P_ + lane];   // y[b,0,0]
            logw = -0.5f * OMEGA_ * mu * mu;
        }
        float mn = logw;
        #pragma unroll
        for (int o = 16; o; o >>= 1) mn = fminf(mn, __shfl_xor_sync(0xffffffffu, mn, o));
        float w = (lane < P_) ? expf(logw - mn) : 0.f;
        float sum = w;
        #pragma unroll
        for (int o = 16; o; o >>= 1) sum += __shfl_xor_sync(0xffffffffu, sum, o);
        float wn = w / sum;
        if (lane < P_) {
            out[OFF_W + b*P_ + lane] = wn;
            slw[lane] = logf(wn + 1e-10f);
        }
    }
    __syncthreads();

    const float tinyf = 1.1754943508222875e-38f;
    const int p = warp;                  // 0..24
    float g = -3.4e38f;
    if (lane < P_) {
        uint32_t i = (uint32_t)((b*P_ + p)*P_ + lane);
        uint32_t o0, o1;
        threefry_0_42(0u, i, o0, o1);
        uint32_t bits = o0 ^ o1;
        float u = __uint_as_float((bits >> 9) | 0x3f800000u) - 1.0f;
        u = u + tinyf;
        u = fmaxf(tinyf, u);
        g = -logf(-logf(u)) + slw[lane];
    }
    int idx = lane;
    #pragma unroll
    for (int o = 16; o; o >>= 1) {
        float og = __shfl_xor_sync(0xffffffffu, g, o);
        int   oi = __shfl_xor_sync(0xffffffffu, idx, o);
        if (og > g || (og == g && oi < idx)) { g = og; idx = oi; }
    }
    if (lane == 0) g_idx[b*P_ + p] = idx;
}

// ---------------------------------------------------------------------------
// Kernel 3: K_res / V_res gather copy. 4 rows per warp, batched loads.
// (b, s, p)-major ordering for L2 reuse on the gather reads.
// ---------------------------------------------------------------------------
__global__ void __launch_bounds__(256) copy_kv_kernel(
    const float* __restrict__ K, const float* __restrict__ V,
    const int* __restrict__ tp, float* __restrict__ out)
{
    const int t = tp ? tp[0] : 512;
    const int warp = threadIdx.x >> 5, lane = threadIdx.x & 31;
    const int q0 = (blockIdx.x * 8 + warp) * 4;

    const float4* kp[4];
    const float4* vp[4];
    size_t dst[4];
    #pragma unroll
    for (int j = 0; j < 4; ++j) {
        int q   = q0 + j;
        int b   = q / (S_ * P_);
        int rem = q - b * (S_ * P_);
        int s   = rem / P_;
        int p   = rem - s * P_;
        int src = g_idx[b*P_ + p];
        size_t srcrow = ((size_t)(b*P_ + src) * S_ + s) * 32;
        if (s == t) {
            kp[j] = reinterpret_cast<const float4*>(g_knew + (b*P_ + src)*D_);
            vp[j] = reinterpret_cast<const float4*>(g_vnew + (b*P_ + src)*D_);
        } else {
            kp[j] = reinterpret_cast<const float4*>(K) + srcrow;
            vp[j] = reinterpret_cast<const float4*>(V) + srcrow;
        }
        dst[j] = ((size_t)(b*P_ + p) * S_ + s) * 32;
    }

    float4 kr[4], vr[4];
    #pragma unroll
    for (int j = 0; j < 4; ++j) kr[j] = kp[j][lane];
    #pragma unroll
    for (int j = 0; j < 4; ++j) vr[j] = vp[j][lane];

    float4* ok = reinterpret_cast<float4*>(out + OFF_K);
    float4* ov = reinterpret_cast<float4*>(out + OFF_V);
    #pragma unroll
    for (int j = 0; j < 4; ++j) ok[dst[j] + lane] = kr[j];
    #pragma unroll
    for (int j = 0; j < 4; ++j) ov[dst[j] + lane] = vr[j];
}

// ---------------------------------------------------------------------------
// Kernel 4: I_new gather, int4-vectorized (4 elems/thread).
// ---------------------------------------------------------------------------
__global__ void copy_i_kernel(const int* __restrict__ I,
                              const int* __restrict__ tp,
                              float* __restrict__ out)
{
    const int t = tp ? tp[0] : 512;
    const int gid = blockIdx.x * blockDim.x + threadIdx.x;
    if (gid >= (B_*P_*S_)/4) return;
    const int base = gid * 4;
    const int b    = base / (P_ * S_);
    const int rem  = base - b * (P_ * S_);
    const int p    = rem >> 10;
    const int s0   = rem & (S_ - 1);
    const int src  = g_idx[b*P_ + p];

    int4 v = *reinterpret_cast<const int4*>(
        I + ((size_t)(b*P_ + src) * S_ + s0));
    int vals[4] = {v.x, v.y, v.z, v.w};
    #pragma unroll
    for (int j = 0; j < 4; ++j)
        if (s0 + j == t) vals[j] = src;

    float4 fv = make_float4((float)vals[0], (float)vals[1],
                            (float)vals[2], (float)vals[3]);
    *reinterpret_cast<float4*>(out + OFF_I + base) = fv;
}

extern "C" void kernel_launch(void* const* d_in, const int* in_sizes, int n_in,
                              void* d_out, int out_size)
{
    const float* x     = (const float*)d_in[0];
    const float* y     = (const float*)d_in[1];
    const float* K     = (const float*)d_in[2];
    const float* V     = (const float*)d_in[3];
    /* w = d_in[4] unused */
    const int*   I     = (const int*)  d_in[5];
    const float* Wq    = (const float*)d_in[6];
    const float* Wk    = (const float*)d_in[7];
    const float* Wv    = (const float*)d_in[8];
    const float* Wo    = (const float*)d_in[9];
    const float* W1    = (const float*)d_in[10];
    const float* b1    = (const float*)d_in[11];
    const float* W2    = (const float*)d_in[12];
    const float* b2    = (const float*)d_in[13];
    const float* Wout  = (const float*)d_in[14];
    const float* bout  = (const float*)d_in[15];
    const float* eps_k = (const float*)d_in[16];
    const float* eps_v = (const float*)d_in[17];
    const float* eps_z = (const float*)d_in[18];
    const int*   tp    = (n_in > 19) ? (const int*)d_in[19] : nullptr;
    float* out = (float*)d_out;

    qkv_kernel<<<BP_/4, 384>>>(x, Wq, Wk, Wv, eps_k, eps_v);
    attn_kernel<<<BP_, 512>>>(K, V, tp);
    mlp_kernel<<<BP_/4, 512>>>(Wo, W1, b1, W2, b2, Wout, bout, eps_z, out);
    resample_kernel<<<B_, 800>>>(y, out);
    copy_i_kernel<<<(B_*P_*S_/4 + 255)/256, 256>>>(I, tp, out);
    copy_kv_kernel<<<BP_ * S_ / 32, 256>>>(K, V, tp, out);
}

// round 8
// speedup vs baseline: 1.0161x; 1.0161x over previous
#include <cuda_runtime.h>
#include <stdint.h>

#define B_ 16
#define P_ 25
#define S_ 1024
#define D_ 128
#define H_ 8
#define DH_ 16
#define DFF_ 512
#define BP_ (B_*P_)
#define SIGMA_ 0.1f
#define OMEGA_ 0.5f

// output layout (flat f32 concat of the reference tuple)
#define OFF_R    0
#define OFF_Z    51200
#define OFF_PRED 102400
#define OFF_W    102800
#define OFF_K    103200
#define OFF_V    52532000
#define OFF_I    104960800

// scratch (allocation-free: __device__ globals)
__device__ __align__(16) float g_knew[BP_*D_];
__device__ __align__(16) float g_vnew[BP_*D_];
__device__ float g_pred[BP_];
__device__ int   g_idx[BP_];

__device__ __forceinline__ uint32_t rotl32(uint32_t x, int d) {
    return (x << d) | (x >> (32 - d));
}

// Threefry-2x32 with key (0, 42)  [jax.random.key(42)]
__device__ __forceinline__ void threefry_0_42(uint32_t x0, uint32_t x1,
                                              uint32_t& o0, uint32_t& o1) {
    const uint32_t k0 = 0u, k1 = 42u;
    const uint32_t k2 = k0 ^ k1 ^ 0x1BD11BDAu;
    uint32_t v0 = x0 + k0, v1 = x1 + k1;
#define TF_R(r) { v0 += v1; v1 = rotl32(v1, r); v1 ^= v0; }
    TF_R(13) TF_R(15) TF_R(26) TF_R(6)
    v0 += k1; v1 += k2 + 1u;
    TF_R(17) TF_R(29) TF_R(16) TF_R(24)
    v0 += k2; v1 += k0 + 2u;
    TF_R(13) TF_R(15) TF_R(26) TF_R(6)
    v0 += k0; v1 += k1 + 3u;
    TF_R(17) TF_R(29) TF_R(16) TF_R(24)
    v0 += k1; v1 += k2 + 4u;
    TF_R(13) TF_R(15) TF_R(26) TF_R(6)
    v0 += k2; v1 += k0 + 5u;
#undef TF_R
    o0 = v0; o1 = v1;
}

// ---------------------------------------------------------------------------
// Kernel 1: fused forward, 2 particles per block. 200 blocks x 512 threads.
// Weight columns are read once per block and used for both particles.
// Dynamic smem: scores sS[2][H][S] = 64KB.
// ---------------------------------------------------------------------------
__global__ void __launch_bounds__(512) fwd_kernel(
    const float* __restrict__ x, const float* __restrict__ K,
    const float* __restrict__ V,
    const float* __restrict__ Wq, const float* __restrict__ Wk,
    const float* __restrict__ Wv, const float* __restrict__ Wo,
    const float* __restrict__ W1, const float* __restrict__ b1,
    const float* __restrict__ W2, const float* __restrict__ b2,
    const float* __restrict__ Wout, const float* __restrict__ bout,
    const float* __restrict__ eps_k, const float* __restrict__ eps_v,
    const float* __restrict__ eps_z,
    const int* __restrict__ tp, float* __restrict__ out)
{
    extern __shared__ float sS[];        // [2][H_][S_] : part*8192 + h*1024 + s
    __shared__ float sx[2][D_], sq[2][D_], sk[2][D_], sv[2][D_];
    __shared__ float sred[4][D_];
    __shared__ float sctx[2][D_], sz[2][D_], sh1[2][DFF_], sr[2][D_];

    const int bp0  = blockIdx.x * 2;
    const int tid  = threadIdx.x;
    const int warp = tid >> 5;
    const int lane = tid & 31;
    const int t    = tp ? tp[0] : 512;

    if (tid < 256) {
        int m = tid >> 7, d = tid & 127;
        sx[m][d] = x[(bp0 + m)*D_ + d];
    }
    __syncthreads();

    // q/k/v projection: thread (sel, col) computes one column for BOTH particles
    {
        const int sel = tid >> 7;        // 0:q 1:k 2:v 3:idle
        const int col = tid & 127;
        if (sel < 3) {
            const float* W = (sel == 0) ? Wq : (sel == 1) ? Wk : Wv;
            float a0 = 0.f, a1 = 0.f;
            #pragma unroll 8
            for (int d = 0; d < D_; ++d) {
                float wv = W[d*D_ + col];
                a0 += sx[0][d] * wv;
                a1 += sx[1][d] * wv;
            }
            if (sel == 0) {
                sq[0][col] = a0; sq[1][col] = a1;
            } else if (sel == 1) {
                a0 += SIGMA_ * eps_k[(bp0  )*D_ + col];
                a1 += SIGMA_ * eps_k[(bp0+1)*D_ + col];
                sk[0][col] = a0; sk[1][col] = a1;
                g_knew[(bp0  )*D_ + col] = a0;
                g_knew[(bp0+1)*D_ + col] = a1;
            } else {
                a0 += SIGMA_ * eps_v[(bp0  )*D_ + col];
                a1 += SIGMA_ * eps_v[(bp0+1)*D_ + col];
                sv[0][col] = a0; sv[1][col] = a1;
                g_vnew[(bp0  )*D_ + col] = a0;
                g_vnew[(bp0+1)*D_ + col] = a1;
            }
        }
    }
    __syncthreads();

    // scores: warp-per-row, both particles per iteration (2 loads in flight)
    {
        const float4* K0 = reinterpret_cast<const float4*>(K + (size_t)(bp0  ) * S_ * D_);
        const float4* K1 = reinterpret_cast<const float4*>(K + (size_t)(bp0+1) * S_ * D_);
        const float4  q0 = reinterpret_cast<const float4*>(sq[0])[lane];
        const float4  q1 = reinterpret_cast<const float4*>(sq[1])[lane];
        const int     head = lane >> 2;
        for (int s = warp; s < t; s += 16) {
            float4 kv0 = K0[(size_t)s * 32 + lane];
            float4 kv1 = K1[(size_t)s * 32 + lane];
            float a0 = q0.x*kv0.x + q0.y*kv0.y + q0.z*kv0.z + q0.w*kv0.w;
            float a1 = q1.x*kv1.x + q1.y*kv1.y + q1.z*kv1.z + q1.w*kv1.w;
            a0 += __shfl_xor_sync(0xffffffffu, a0, 1);
            a0 += __shfl_xor_sync(0xffffffffu, a0, 2);
            a1 += __shfl_xor_sync(0xffffffffu, a1, 1);
            a1 += __shfl_xor_sync(0xffffffffu, a1, 2);
            if ((lane & 3) == 0) {
                sS[head*S_ + s]             = a0 * 0.25f;
                sS[H_*S_ + head*S_ + s]     = a1 * 0.25f;
            }
        }
    }
    // s == t uses the freshly computed k
    if (tid < 16) {
        int part = tid >> 3, h = tid & 7;
        float a = 0.f;
        #pragma unroll
        for (int d = 0; d < DH_; ++d) a += sq[part][h*DH_ + d] * sk[part][h*DH_ + d];
        sS[part*H_*S_ + h*S_ + t] = a * 0.25f;
    }
    __syncthreads();

    // softmax: 16 warps = 2 particles x 8 heads
    {
        int part = warp >> 3, h = warp & 7;
        float* row = sS + part*H_*S_ + h*S_;
        float m = -3.4e38f;
        for (int s = lane; s <= t; s += 32) m = fmaxf(m, row[s]);
        #pragma unroll
        for (int o = 16; o; o >>= 1) m = fmaxf(m, __shfl_xor_sync(0xffffffffu, m, o));
        float sum = 0.f;
        for (int s = lane; s <= t; s += 32) {
            float e = expf(row[s] - m);
            row[s] = e; sum += e;
        }
        #pragma unroll
        for (int o = 16; o; o >>= 1) sum += __shfl_xor_sync(0xffffffffu, sum, o);
        float inv = 1.f / sum;
        for (int s = lane; s <= t; s += 32) row[s] *= inv;
    }
    __syncthreads();

    // ctx: per particle, 2-way split over s, unrolled x4
    {
        const int part = tid >> 8;
        const int idx  = tid & 255;
        const int dim  = idx & 127;
        const int sub  = idx >> 7;
        const int h    = dim >> 4;
        const float* row  = sS + part*H_*S_ + h*S_;
        const float* Vrow = V + (size_t)(bp0 + part) * S_ * D_ + dim;
        float c0 = 0.f, c1 = 0.f, c2 = 0.f, c3 = 0.f;
        int s = sub;
        for (; s + 6 < t; s += 8) {
            float v0 = Vrow[(size_t)(s    ) * D_];
            float v1 = Vrow[(size_t)(s + 2) * D_];
            float v2 = Vrow[(size_t)(s + 4) * D_];
            float v3 = Vrow[(size_t)(s + 6) * D_];
            c0 += row[s    ] * v0;
            c1 += row[s + 2] * v1;
            c2 += row[s + 4] * v2;
            c3 += row[s + 6] * v3;
        }
        for (; s <= t; s += 2) {
            float vv = (s == t) ? sv[part][dim] : Vrow[(size_t)s * D_];
            c0 += row[s] * vv;
        }
        sred[part*2 + sub][dim] = (c0 + c1) + (c2 + c3);
    }
    __syncthreads();
    if (tid < 256) {
        int part = tid >> 7, dim = tid & 127;
        sctx[part][dim] = sred[part*2][dim] + sred[part*2 + 1][dim];
    }
    __syncthreads();

    // z = ctx @ Wo + sigma*eps_z : thread (half, part, col), 64-MAC halves
    {
        const int col  = tid & 127;
        const int part = (tid >> 7) & 1;
        const int half = tid >> 8;
        float a = 0.f;
        #pragma unroll
        for (int d = half*64; d < half*64 + 64; ++d) a += sctx[part][d] * Wo[d*D_ + col];
        sred[half*2 + part][col] = a;
    }
    __syncthreads();
    if (tid < 256) {
        int part = tid >> 7, col = tid & 127;
        float a = sred[part][col] + sred[2 + part][col]
                + SIGMA_ * eps_z[(bp0 + part)*D_ + col];
        sz[part][col] = a;
        out[OFF_Z + (bp0 + part)*D_ + col] = a;
    }
    __syncthreads();

    // h1 = relu(z @ W1 + b1): thread f computes both particles (W1 col once)
    {
        const int f = tid;
        float a0 = b1[f], a1 = a0;
        #pragma unroll 8
        for (int d = 0; d < D_; ++d) {
            float wv = W1[d*DFF_ + f];
            a0 += sz[0][d] * wv;
            a1 += sz[1][d] * wv;
        }
        sh1[0][f] = fmaxf(a0, 0.f);
        sh1[1][f] = fmaxf(a1, 0.f);
    }
    __syncthreads();

    // r = h1 @ W2 + b2: thread (half, part, col), 256-MAC halves
    {
        const int col  = tid & 127;
        const int part = (tid >> 7) & 1;
        const int half = tid >> 8;
        float a = 0.f;
        #pragma unroll 8
        for (int f = half*256; f < half*256 + 256; ++f) a += sh1[part][f] * W2[f*D_ + col];
        sred[half*2 + part][col] = a;
    }
    __syncthreads();
    if (tid < 256) {
        int part = tid >> 7, col = tid & 127;
        float a = b2[col] + sred[part][col] + sred[2 + part][col];
        sr[part][col] = a;
        out[OFF_R + (bp0 + part)*D_ + col] = a;
    }
    __syncthreads();

    // pred = r @ Wout + bout (F == 1): warps 0,1 = particles 0,1
    if (warp < 2) {
        float a = 0.f;
        #pragma unroll
        for (int d = lane; d < D_; d += 32) a += sr[warp][d] * Wout[d];
        #pragma unroll
        for (int o = 16; o; o >>= 1) a += __shfl_xor_sync(0xffffffffu, a, o);
        if (lane == 0) {
            a += bout[0];
            g_pred[bp0 + warp] = a;
            out[OFF_PRED + bp0 + warp] = a;
        }
    }
}

// ---------------------------------------------------------------------------
// Kernel 2: weights + categorical resampling. 16 blocks x 256 (8 warps).
// ---------------------------------------------------------------------------
__global__ void __launch_bounds__(256) resample_kernel(
    const float* __restrict__ y, float* __restrict__ out)
{
    const int b = blockIdx.x;
    const int warp = threadIdx.x >> 5;
    const int lane = threadIdx.x & 31;
    __shared__ float slw[P_];

    if (warp == 0) {
        float logw = 3.4e38f;
        if (lane < P_) {
            float mu = y[b*4] - g_pred[b*P_ + lane];   // y[b,0,0]
            logw = -0.5f * OMEGA_ * mu * mu;
        }
        float mn = logw;
        #pragma unroll
        for (int o = 16; o; o >>= 1) mn = fminf(mn, __shfl_xor_sync(0xffffffffu, mn, o));
        float w = (lane < P_) ? expf(logw - mn) : 0.f;
        float sum = w;
        #pragma unroll
        for (int o = 16; o; o >>= 1) sum += __shfl_xor_sync(0xffffffffu, sum, o);
        float wn = w / sum;
        if (lane < P_) {
            out[OFF_W + b*P_ + lane] = wn;
            slw[lane] = logf(wn + 1e-10f);
        }
    }
    __syncthreads();

    const float tinyf = 1.1754943508222875e-38f;
    for (int p = warp; p < P_; p += 8) {
        float g = -3.4e38f;
        if (lane < P_) {
            uint32_t i = (uint32_t)((b*P_ + p)*P_ + lane);
            uint32_t o0, o1;
            threefry_0_42(0u, i, o0, o1);
            uint32_t bits = o0 ^ o1;
            float u = __uint_as_float((bits >> 9) | 0x3f800000u) - 1.0f;
            u = u + tinyf;
            u = fmaxf(tinyf, u);
            g = -logf(-logf(u)) + slw[lane];
        }
        int idx = lane;
        #pragma unroll
        for (int o = 16; o; o >>= 1) {
            float og = __shfl_xor_sync(0xffffffffu, g, o);
            int   oi = __shfl_xor_sync(0xffffffffu, idx, o);
            if (og > g || (og == g && oi < idx)) { g = og; idx = oi; }
        }
        if (lane == 0) g_idx[b*P_ + p] = idx;
    }
}

// ---------------------------------------------------------------------------
// Kernel 3: K_res / V_res gather copy + fused I_new gather.
// 4 rows per warp, loads batched into registers (MLP 8). (b,s,p)-major for
// L2 reuse. Lanes 0-3 additionally emit the I_new element for their row.
// ---------------------------------------------------------------------------
__global__ void __launch_bounds__(256) copy_kv_kernel(
    const float* __restrict__ K, const float* __restrict__ V,
    const int* __restrict__ I,
    const int* __restrict__ tp, float* __restrict__ out)
{
    const int t = tp ? tp[0] : 512;
    const int warp = threadIdx.x >> 5, lane = threadIdx.x & 31;
    const int q0 = (blockIdx.x * 8 + warp) * 4;

    const float4* kp[4];
    const float4* vp[4];
    size_t dst[4];
    int bj[4], pj[4], sj[4], srcj[4];
    #pragma unroll
    for (int j = 0; j < 4; ++j) {
        int q   = q0 + j;
        int b   = q / (S_ * P_);
        int rem = q - b * (S_ * P_);
        int s   = rem / P_;
        int p   = rem - s * P_;
        int src = g_idx[b*P_ + p];
        bj[j] = b; pj[j] = p; sj[j] = s; srcj[j] = src;
        size_t srcrow = ((size_t)(b*P_ + src) * S_ + s) * 32;
        if (s == t) {
            kp[j] = reinterpret_cast<const float4*>(g_knew + (b*P_ + src)*D_);
            vp[j] = reinterpret_cast<const float4*>(g_vnew + (b*P_ + src)*D_);
        } else {
            kp[j] = reinterpret_cast<const float4*>(K) + srcrow;
            vp[j] = reinterpret_cast<const float4*>(V) + srcrow;
        }
        dst[j] = ((size_t)(b*P_ + p) * S_ + s) * 32;
    }

    float4 kr[4], vr[4];
    #pragma unroll
    for (int j = 0; j < 4; ++j) kr[j] = kp[j][lane];
    #pragma unroll
    for (int j = 0; j < 4; ++j) vr[j] = vp[j][lane];

    float4* ok = reinterpret_cast<float4*>(out + OFF_K);
    float4* ov = reinterpret_cast<float4*>(out + OFF_V);
    #pragma unroll
    for (int j = 0; j < 4; ++j) ok[dst[j] + lane] = kr[j];
    #pragma unroll
    for (int j = 0; j < 4; ++j) ov[dst[j] + lane] = vr[j];

    // fused I_new: lanes 0-3 handle one row each
    if (lane < 4) {
        int j = lane;
        int val = (sj[j] == t) ? srcj[j]
                : I[((size_t)(bj[j]*P_ + srcj[j])) * S_ + sj[j]];
        out[OFF_I + ((size_t)(bj[j]*P_ + pj[j]) * S_ + sj[j])] = (float)val;
    }
}

extern "C" void kernel_launch(void* const* d_in, const int* in_sizes, int n_in,
                              void* d_out, int out_size)
{
    const float* x     = (const float*)d_in[0];
    const float* y     = (const float*)d_in[1];
    const float* K     = (const float*)d_in[2];
    const float* V     = (const float*)d_in[3];
    /* w = d_in[4] unused */
    const int*   I     = (const int*)  d_in[5];
    const float* Wq    = (const float*)d_in[6];
    const float* Wk    = (const float*)d_in[7];
    const float* Wv    = (const float*)d_in[8];
    const float* Wo    = (const float*)d_in[9];
    const float* W1    = (const float*)d_in[10];
    const float* b1    = (const float*)d_in[11];
    const float* W2    = (const float*)d_in[12];
    const float* b2    = (const float*)d_in[13];
    const float* Wout  = (const float*)d_in[14];
    const float* bout  = (const float*)d_in[15];
    const float* eps_k = (const float*)d_in[16];
    const float* eps_v = (const float*)d_in[17];
    const float* eps_z = (const float*)d_in[18];
    const int*   tp    = (n_in > 19) ? (const int*)d_in[19] : nullptr;
    float* out = (float*)d_out;

    const int dynsmem = 2 * H_ * S_ * (int)sizeof(float);   // 64 KB
    cudaFuncSetAttribute(fwd_kernel,
                         cudaFuncAttributeMaxDynamicSharedMemorySize, dynsmem);

    fwd_kernel<<<BP_/2, 512, dynsmem>>>(x, K, V, Wq, Wk, Wv, Wo, W1, b1, W2, b2,
                                        Wout, bout, eps_k, eps_v, eps_z, tp, out);
    resample_kernel<<<B_, 256>>>(y, out);
    copy_kv_kernel<<<BP_ * S_ / 32, 256>>>(K, V, I, tp, out);
}